// round 14
// baseline (speedup 1.0000x reference)
#include <cuda_runtime.h>
#include <cuda_fp16.h>

#define B_ 512
#define T_ 365
#define D_ 16
#define S_ 32
#define H_ 256

/* ---- SMEM layout (bytes) ---- */
#define S0 296              /* fp16 row stride A0/W0: 256 h + 16 x_hi + 16 x_res + 8 pad */
#define S1 520              /* fp16 row stride W1: 512 + 8 pad */
#define S1N 264             /* fp16 row stride A1: 256 h1 + 8 pad */
#define W0_OFF  0           /* 64*296*2 = 37888 */
#define W1_OFF  37888       /* 64*520*2 = 66560 */
#define A0A_OFF 104448      /* 32*296*2 = 18944 */
#define A0B_OFF 123392      /* 18944 */
#define A1A_OFF 142336      /* 32*264*2 = 16896 */
#define A1B_OFF 159232      /* 16896 */
#define GB0_OFF 176128      /* 32*66*4 = 8448 */
#define GB1_OFF 184576      /* 8448 */
#define BS_OFF  193024      /* 512 */
#define SMEM_BYTES 193536   /* <= 232448 */

#define NBH (B_ * H_)

/* ---- device globals ---- */
__device__ float  g_h0f[NBH];
__device__ __half g_h0x[2 * NBH];   /* parity buffers: ep0(t) writes [t&1] */
__device__ __half g_h1x[2 * NBH];   /* ep1(t) writes [t&1]; [1] holds init h1(-1) */
__device__ unsigned g_cnt[16];      /* [2*gp]=subgroup A, [2*gp+1]=subgroup B */

/* ---- prep kernel ---- */
__global__ void k_h0(const float* __restrict__ xst, const float* __restrict__ Ws,
                     const float* __restrict__ bs) {
    int e = blockIdx.x * 256 + threadIdx.x;
    if (blockIdx.x == 0 && threadIdx.x < 16) g_cnt[threadIdx.x] = 0;
    if (e >= NBH) return;
    int b = e >> 8, j = e & 255;
    float s = bs[j];
#pragma unroll
    for (int k = 0; k < S_; k++)
        s += xst[b * S_ + k] * Ws[j * S_ + k];
    g_h0f[e] = s;
    __half h = __float2half(s);
    g_h1x[e] = h;
    g_h1x[NBH + e] = h;     /* buf 1 = h1(-1) init, read at iteration-0 reload */
}

/* ---- helpers ---- */
__device__ __forceinline__ unsigned su32(const void* p) {
    unsigned a;
    asm("{ .reg .u64 t; cvta.to.shared.u64 t, %1; cvt.u32.u64 %0, t; }" : "=r"(a) : "l"(p));
    return a;
}
__device__ __forceinline__ float sigm(float x) {
    return __fdividef(1.0f, 1.0f + __expf(-x));
}
__device__ __forceinline__ float tanhe(float x) {
    return __fdividef(2.0f, 1.0f + __expf(-2.0f * x)) - 1.0f;
}

#define LDSM4(r0,r1,r2,r3,a) \
    asm volatile("ldmatrix.sync.aligned.m8n8.x4.shared.b16 {%0,%1,%2,%3}, [%4];" \
        : "=r"(r0), "=r"(r1), "=r"(r2), "=r"(r3) : "r"(a))
#define MMA(d,a0,a1,a2,a3,b0,b1) \
    asm volatile("mma.sync.aligned.m16n8k16.row.col.f32.f16.f16.f32 " \
        "{%0,%1,%2,%3},{%4,%5,%6,%7},{%8,%9},{%0,%1,%2,%3};" \
        : "+f"((d)[0]), "+f"((d)[1]), "+f"((d)[2]), "+f"((d)[3]) \
        : "r"(a0), "r"(a1), "r"(a2), "r"(a3), "r"(b0), "r"(b1))

#define CP_A16(sm, gp) \
    asm volatile("cp.async.cg.shared.global [%0], [%1], 16;" :: "r"(sm), "l"(gp) : "memory")
#define CP_COMMIT() asm volatile("cp.async.commit_group;" ::: "memory")
#define CP_WAIT3()  asm volatile("cp.async.wait_group 3;" ::: "memory")
#define CP_WAIT2()  asm volatile("cp.async.wait_group 2;" ::: "memory")
#define CP_WAIT1()  asm volatile("cp.async.wait_group 1;" ::: "memory")
#define CP_WAIT0()  asm volatile("cp.async.wait_group 0;" ::: "memory")

/* warp tile M16xN16: 1 A frag + 1 B frag, 2 MMAs per kstep */
__device__ __forceinline__ void gemm16(unsigned aA, unsigned wA, int ksteps,
                                       float acc[2][4]) {
#pragma unroll 2
    for (int ks = 0; ks < ksteps; ks++) {
        unsigned p0,p1,p2,p3, b0,b1,b2,b3;
        LDSM4(p0,p1,p2,p3, aA);
        LDSM4(b0,b1,b2,b3, wA);
        MMA(acc[0], p0,p1,p2,p3, b0,b1);
        MMA(acc[1], p0,p1,p2,p3, b2,b3);
        aA += 32; wA += 32;
    }
}

__device__ __forceinline__ void frag_store16(float* GBf, const float acc[2][4],
                                             int mh, int nq, int lane) {
#pragma unroll
    for (int nt = 0; nt < 2; nt++) {
        int m = mh * 16 + (lane >> 2);
        int n = nq * 16 + nt * 8 + (lane & 3) * 2;
        *(float2*)&GBf[m * 66 + n]       = make_float2(acc[nt][0], acc[nt][1]);
        *(float2*)&GBf[(m + 8) * 66 + n] = make_float2(acc[nt][2], acc[nt][3]);
    }
}

/* split barrier: acquire wait on a monotonic counter */
__device__ __forceinline__ void g_wait(unsigned* c, unsigned target) {
    if (threadIdx.x == 0) {
        unsigned v;
        do {
            asm volatile("ld.acquire.gpu.global.u32 %0, [%1];" : "=r"(v) : "l"(c) : "memory");
        } while (v < target);
    }
    __syncthreads();
}

/* stage x_t as hi/res fp16 pair into a 32-row A0 buffer (256 threads) */
__device__ __forceinline__ void stage_x32(char* smem, unsigned a0off,
                                          const float* x, int growbase,
                                          int t, int tid) {
    int row = tid >> 3, kq = (tid & 7) * 2;
    const float2 v = __ldg((const float2*)
        (x + (size_t)(growbase + row) * T_ * D_ + (size_t)t * D_ + kq));
    __half h0 = __float2half(v.x), h1 = __float2half(v.y);
    float r0 = v.x - __half2float(h0), r1 = v.y - __half2float(h1);
    __half2 hA = __halves2half2(h0, h1);
    __half2 rA = __floats2half2_rn(r0, r1);
    char* base = smem + a0off + row * (S0 * 2);
    *(unsigned*)(base + (256 + kq) * 2) = *(unsigned*)&hA;
    *(unsigned*)(base + (272 + kq) * 2) = *(unsigned*)&rA;
}

/* async reload of a 32-row h buffer (16KB) */
__device__ __forceinline__ void reload32(unsigned sb, unsigned dstoff, int strideh,
                                         const __half* src, int growbase, int tid) {
    for (int e = tid; e < 1024; e += 256) {
        int row = e >> 5, ch = e & 31;
        unsigned dst = sb + dstoff + (unsigned)(row * (strideh * 2) + ch * 16);
        CP_A16(dst, (const char*)(src + (size_t)(growbase + row) * H_) + ch * 16);
    }
}

/* ---- main persistent kernel: 128 CTAs = 8 gp x 16 ranks, 256 thr ----
   R14: TWO independent 32-row recurrence chains per CTA (subgroups A/B,
   separate barriers). Barrier waits hide behind the other subgroup's
   compute; cp.async ring (4 groups) hides reload latency.              */
__global__ void __launch_bounds__(256, 1)
lstm_main(const float* __restrict__ x,
          const float* __restrict__ Wih0, const float* __restrict__ Whh0,
          const float* __restrict__ Wih1, const float* __restrict__ Whh1,
          const float* __restrict__ bih0, const float* __restrict__ bhh0,
          const float* __restrict__ bih1, const float* __restrict__ bhh1,
          const float* __restrict__ Wo, const float* __restrict__ bo,
          float* __restrict__ out)
{
    extern __shared__ char smem[];
    const int tid  = threadIdx.x;
    const int lane = tid & 31;
    const int wid  = tid >> 5;
    const int mh = wid & 1, nq = wid >> 1;       /* M16 x N16 warp grid (2x4) */
    const int gp   = blockIdx.x >> 4;
    const int rank = blockIdx.x & 15;
    const int jl = tid & 15;
    const int rgrp = tid >> 4;                   /* 0..15, owns rows 2*rgrp..+1 */
    const int rbA = gp * 64;                     /* subgroup A global row base */
    const int rbB = gp * 64 + 32;

    __half* W0s = (__half*)(smem + W0_OFF);
    __half* W1s = (__half*)(smem + W1_OFF);
    float*  GB0 = (float*)(smem + GB0_OFF);
    float*  GB1 = (float*)(smem + GB1_OFF);
    float*  b0s = (float*)(smem + BS_OFF);
    float*  b1s = b0s + 64;

    unsigned* cA = &g_cnt[2 * gp];
    unsigned* cB = &g_cnt[2 * gp + 1];

    /* ---- one-time weight staging ---- */
    for (int e = tid; e < 64 * S0; e += 256) {
        int n = e / S0, k = e - n * S0;
        int wr = (n >> 4) * H_ + rank * 16 + (n & 15);
        float v = 0.0f;
        if (k < 256)      v = Whh0[wr * H_ + k];
        else if (k < 272) v = Wih0[wr * D_ + (k - 256)];
        else if (k < 288) v = Wih0[wr * D_ + (k - 272)];
        W0s[e] = __float2half(v);
    }
    for (int e = tid; e < 64 * S1; e += 256) {
        int n = e / S1, k = e - n * S1;
        int wr = (n >> 4) * H_ + rank * 16 + (n & 15);
        float v = 0.0f;
        if (k < 256)      v = Wih1[wr * H_ + k];
        else if (k < 512) v = Whh1[wr * H_ + (k - 256)];
        W1s[e] = __float2half(v);
    }
    if (tid < 64) {
        int wr = (tid >> 4) * H_ + rank * 16 + (tid & 15);
        b0s[tid] = bih0[wr] + bhh0[wr];
        b1s[tid] = bih1[wr] + bhh1[wr];
    }
    const float woreg = __ldg(Wo + rank * 16 + jl);
    const float bo0   = __ldg(bo);

    /* ---- zero this gp's output rows (head atomics at it>=1 gated behind
            waitS(0), which follows every rank's prologue) ---- */
    {
        float* ob = out + (size_t)gp * 64 * T_;
        for (int i = rank * 256 + tid; i < 64 * T_; i += 4096) ob[i] = 0.0f;
    }

    /* ---- initial A0a/A0b h-cols <- fp16(g_h0f) (g_h0f never written here:
            race-free prologue); stage x(0) for both subgroups ---- */
    for (int e = tid; e < 64 * 128; e += 256) {
        int row = e >> 7, c2 = e & 127;
        const float2 v = *(const float2*)
            (g_h0f + (size_t)(gp * 64 + row) * H_ + c2 * 2);
        __half2 h = __floats2half2_rn(v.x, v.y);
        unsigned off = (row < 32) ? (unsigned)(A0A_OFF + row * (S0 * 2))
                                  : (unsigned)(A0B_OFF + (row - 32) * (S0 * 2));
        *(unsigned*)(smem + off + c2 * 4) = *(unsigned*)&h;
    }
    stage_x32(smem, A0A_OFF, x, rbA, 0, tid);
    stage_x32(smem, A0B_OFF, x, rbB, 0, tid);

    /* ---- c-state: 2 rows x 1 j per thread per subgroup ---- */
    float c0a[2], c1a[2], c0b[2], c1b[2];
#pragma unroll
    for (int rr = 0; rr < 2; rr++) {
        float va = g_h0f[(size_t)(rbA + rgrp * 2 + rr) * H_ + rank * 16 + jl];
        float vb = g_h0f[(size_t)(rbB + rgrp * 2 + rr) * H_ + rank * 16 + jl];
        c0a[rr] = va; c1a[rr] = va;
        c0b[rr] = vb; c1b[rr] = vb;
    }
    __syncthreads();

    /* ldmatrix addressing (M16 x N16 warp tile) */
    const unsigned sb = su32(smem);
    const int aRow = mh * 16 + (lane & 7) + ((lane >> 3) & 1) * 8;
    const int aCol = (lane >> 4) * 8;
    const unsigned a0aA = sb + A0A_OFF + (unsigned)(aRow * S0 + aCol) * 2;
    const unsigned a0bA = sb + A0B_OFF + (unsigned)(aRow * S0 + aCol) * 2;
    const unsigned a1aA = sb + A1A_OFF + (unsigned)(aRow * S1N + aCol) * 2;
    const unsigned a1bA = sb + A1B_OFF + (unsigned)(aRow * S1N + aCol) * 2;
    const int nrow = nq * 16 + ((lane >> 4) & 1) * 8 + (lane & 7);
    const int wCol = ((lane >> 3) & 1) * 8;
    const unsigned w0a = sb + W0_OFF + (unsigned)(nrow * S0 + wCol) * 2;
    const unsigned w1a = sb + W1_OFF + (unsigned)(nrow * S1 + wCol) * 2;

    unsigned btA = 0, btB = 0;

    for (int it = 0; it <= T_; it++) {
        /* ================= subgroup A compute ================= */
        CP_WAIT3();                 /* A0a (h0a(it-1)) landed */
        __syncthreads();
        if (it < T_) {
            float acc[2][4] = {};
            gemm16(a0aA, w0a, 18, acc);          /* [h0a|x_hi|x_res] @ W0^T */
            frag_store16(GB0, acc, mh, nq, lane);
        }
        CP_WAIT2();                 /* A1a (h1a(it-2)) landed */
        __syncthreads();
        if (it > 0) {
            float acc[2][4] = {};
            gemm16(a0aA, w1a, 16, acc);          /* h0a(it-1) @ Wih1^T */
            gemm16(a1aA, w1a + 512, 16, acc);    /* h1a(it-2) @ Whh1^T */
            frag_store16(GB1, acc, mh, nq, lane);
        }
        __syncthreads();

        /* epilogue A: ep0 -> h0a(it), ep1 -> h1a(it-1) + head */
        if (it < T_) {
            __half* dst = g_h0x + (size_t)(it & 1) * NBH;
#pragma unroll
            for (int rr = 0; rr < 2; rr++) {
                int r = rgrp * 2 + rr;
                float gi = GB0[r * 66 +      jl] + b0s[jl];
                float gf = GB0[r * 66 + 16 + jl] + b0s[16 + jl];
                float gg = GB0[r * 66 + 32 + jl] + b0s[32 + jl];
                float go = GB0[r * 66 + 48 + jl] + b0s[48 + jl];
                float iv = sigm(gi), fv = sigm(gf), gv = tanhe(gg), ov = sigm(go);
                c0a[rr] = fv * c0a[rr] + iv * gv;
                dst[(size_t)(rbA + r) * H_ + rank * 16 + jl] =
                    __float2half(ov * tanhe(c0a[rr]));
            }
        }
        if (it > 0) {
            __half* dst = g_h1x + (size_t)((it + 1) & 1) * NBH;
            float p[2];
#pragma unroll
            for (int rr = 0; rr < 2; rr++) {
                int r = rgrp * 2 + rr;
                float gi = GB1[r * 66 +      jl] + b1s[jl];
                float gf = GB1[r * 66 + 16 + jl] + b1s[16 + jl];
                float gg = GB1[r * 66 + 32 + jl] + b1s[32 + jl];
                float go = GB1[r * 66 + 48 + jl] + b1s[48 + jl];
                float iv = sigm(gi), fv = sigm(gf), gv = tanhe(gg), ov = sigm(go);
                c1a[rr] = fv * c1a[rr] + iv * gv;
                float h = ov * tanhe(c1a[rr]);
                dst[(size_t)(rbA + r) * H_ + rank * 16 + jl] = __float2half(h);
                p[rr] = h * woreg;
            }
#pragma unroll
            for (int off = 1; off < 16; off <<= 1)
#pragma unroll
                for (int rr = 0; rr < 2; rr++)
                    p[rr] += __shfl_xor_sync(0xffffffffu, p[rr], off);
            if (jl == 0) {
#pragma unroll
                for (int rr = 0; rr < 2; rr++) {
                    float v = p[rr];
                    if (rank == 0) v += bo0;
                    atomicAdd(&out[(size_t)(rbA + rgrp * 2 + rr) * T_ + (it - 1)], v);
                }
            }
        }
        __threadfence();
        __syncthreads();
        if (it < T_ && tid == 0)
            asm volatile("red.release.gpu.global.add.u32 [%0], %1;"
                         :: "l"(cA), "r"(1u) : "memory");

        /* ================= subgroup B compute ================= */
        CP_WAIT1();                 /* A0b landed */
        __syncthreads();
        if (it < T_) {
            float acc[2][4] = {};
            gemm16(a0bA, w0a, 18, acc);
            frag_store16(GB0, acc, mh, nq, lane);
        }
        CP_WAIT0();                 /* A1b landed */
        __syncthreads();
        if (it > 0) {
            float acc[2][4] = {};
            gemm16(a0bA, w1a, 16, acc);
            gemm16(a1bA, w1a + 512, 16, acc);
            frag_store16(GB1, acc, mh, nq, lane);
        }
        __syncthreads();

        if (it < T_) {
            __half* dst = g_h0x + (size_t)(it & 1) * NBH;
#pragma unroll
            for (int rr = 0; rr < 2; rr++) {
                int r = rgrp * 2 + rr;
                float gi = GB0[r * 66 +      jl] + b0s[jl];
                float gf = GB0[r * 66 + 16 + jl] + b0s[16 + jl];
                float gg = GB0[r * 66 + 32 + jl] + b0s[32 + jl];
                float go = GB0[r * 66 + 48 + jl] + b0s[48 + jl];
                float iv = sigm(gi), fv = sigm(gf), gv = tanhe(gg), ov = sigm(go);
                c0b[rr] = fv * c0b[rr] + iv * gv;
                dst[(size_t)(rbB + r) * H_ + rank * 16 + jl] =
                    __float2half(ov * tanhe(c0b[rr]));
            }
        }
        if (it > 0) {
            __half* dst = g_h1x + (size_t)((it + 1) & 1) * NBH;
            float p[2];
#pragma unroll
            for (int rr = 0; rr < 2; rr++) {
                int r = rgrp * 2 + rr;
                float gi = GB1[r * 66 +      jl] + b1s[jl];
                float gf = GB1[r * 66 + 16 + jl] + b1s[16 + jl];
                float gg = GB1[r * 66 + 32 + jl] + b1s[32 + jl];
                float go = GB1[r * 66 + 48 + jl] + b1s[48 + jl];
                float iv = sigm(gi), fv = sigm(gf), gv = tanhe(gg), ov = sigm(go);
                c1b[rr] = fv * c1b[rr] + iv * gv;
                float h = ov * tanhe(c1b[rr]);
                dst[(size_t)(rbB + r) * H_ + rank * 16 + jl] = __float2half(h);
                p[rr] = h * woreg;
            }
#pragma unroll
            for (int off = 1; off < 16; off <<= 1)
#pragma unroll
                for (int rr = 0; rr < 2; rr++)
                    p[rr] += __shfl_xor_sync(0xffffffffu, p[rr], off);
            if (jl == 0) {
#pragma unroll
                for (int rr = 0; rr < 2; rr++) {
                    float v = p[rr];
                    if (rank == 0) v += bo0;
                    atomicAdd(&out[(size_t)(rbB + rgrp * 2 + rr) * T_ + (it - 1)], v);
                }
            }
        }
        __threadfence();
        __syncthreads();
        if (it < T_ && tid == 0)
            asm volatile("red.release.gpu.global.add.u32 [%0], %1;"
                         :: "l"(cB), "r"(1u) : "memory");

        if (it == T_) break;

        /* stage x(it+1): last reads of x-cols were GEMM0(it), syncs passed */
        if (it + 1 < T_) {
            stage_x32(smem, A0A_OFF, x, rbA, it + 1, tid);
            stage_x32(smem, A0B_OFF, x, rbB, it + 1, tid);
        }

        /* ---- waits + async reloads (4-group ring) ----
           waitA arrived a full B-phase ago -> skew absorbed.            */
        const __half* s0 = g_h0x + (size_t)(it & 1) * NBH;
        const __half* s1 = g_h1x + (size_t)((it + 1) & 1) * NBH;  /* h1(it-1); it=0 -> init */

        btA += 16;
        g_wait(cA, btA);
        reload32(sb, A0A_OFF, S0, s0, rbA, tid);  CP_COMMIT();
        reload32(sb, A1A_OFF, S1N, s1, rbA, tid); CP_COMMIT();

        btB += 16;
        g_wait(cB, btB);
        reload32(sb, A0B_OFF, S0, s0, rbB, tid);  CP_COMMIT();
        reload32(sb, A1B_OFF, S1N, s1, rbB, tid); CP_COMMIT();
        /* no sync: next iteration starts with CP_WAIT3 + __syncthreads */
    }
}

/* ---------------- launch ---------------- */
extern "C" void kernel_launch(void* const* d_in, const int* in_sizes, int n_in,
                              void* d_out, int out_size) {
    const float* x    = (const float*)d_in[0];
    const float* xst  = (const float*)d_in[1];
    const float* Wih0 = (const float*)d_in[2];
    const float* Whh0 = (const float*)d_in[3];
    const float* bih0 = (const float*)d_in[4];
    const float* bhh0 = (const float*)d_in[5];
    const float* Wih1 = (const float*)d_in[6];
    const float* Whh1 = (const float*)d_in[7];
    const float* bih1 = (const float*)d_in[8];
    const float* bhh1 = (const float*)d_in[9];
    const float* Ws   = (const float*)d_in[10];
    const float* bs   = (const float*)d_in[11];
    const float* Wo   = (const float*)d_in[12];
    const float* bo   = (const float*)d_in[13];
    float* out = (float*)d_out;

    cudaFuncSetAttribute(lstm_main, cudaFuncAttributeMaxDynamicSharedMemorySize,
                         SMEM_BYTES);

    k_h0<<<(NBH + 255) / 256, 256>>>(xst, Ws, bs);
    lstm_main<<<128, 256, SMEM_BYTES>>>(x, Wih0, Whh0, Wih1, Whh1,
                                        bih0, bhh0, bih1, bhh1, Wo, bo, out);
}

// round 15
// speedup vs baseline: 2.0060x; 2.0060x over previous
#include <cuda_runtime.h>
#include <cuda_fp16.h>

#define B_ 512
#define T_ 365
#define D_ 16
#define S_ 32
#define H_ 256

/* ---- SMEM layout (bytes) ---- */
#define S0 296              /* fp16 row stride of A0/W0: 256 h + 16 x_hi + 16 x_res + 8 pad */
#define S1 520              /* fp16 row stride of W1: 512 + 8 pad */
#define S1N 264             /* fp16 row stride of A1: 256 h1 + 8 pad */
#define W0_OFF 0            /* 64*296*2 = 37888 */
#define W1_OFF 37888        /* 64*520*2 = 66560 */
#define A0_OFF 104448       /* 37888 */
#define A1_OFF 142336       /* 64*264*2 = 33792 */
#define GB0_OFF 176128      /* 64*66*4 = 16896 */
#define GB1_OFF 193024      /* 16896 */
#define BS_OFF 209920       /* 512 */
#define SMEM_BYTES 210432   /* <= 232448 */

#define NBH (B_ * H_)

/* ---- device globals ---- */
__device__ float  g_h0f[NBH];
__device__ __half g_h0x[2 * NBH];   /* parity buffers: ep0(t) writes [t&1] */
__device__ __half g_h1x[2 * NBH];   /* ep1(t) writes [t&1]; [1] holds init h1(-1) */
__device__ unsigned g_cnt[8];

/* ---- prep kernel ---- */
__global__ void k_h0(const float* __restrict__ xst, const float* __restrict__ Ws,
                     const float* __restrict__ bs) {
    int e = blockIdx.x * 256 + threadIdx.x;
    if (blockIdx.x == 0 && threadIdx.x < 8) g_cnt[threadIdx.x] = 0;
    if (e >= NBH) return;
    int b = e >> 8, j = e & 255;
    float s = bs[j];
#pragma unroll
    for (int k = 0; k < S_; k++)
        s += xst[b * S_ + k] * Ws[j * S_ + k];
    g_h0f[e] = s;
    __half h = __float2half(s);
    g_h1x[e] = h;
    g_h1x[NBH + e] = h;     /* buf 1 = h1(-1) init, read at iteration-0 reload */
}

/* ---- helpers ---- */
__device__ __forceinline__ unsigned su32(const void* p) {
    unsigned a;
    asm("{ .reg .u64 t; cvta.to.shared.u64 t, %1; cvt.u32.u64 %0, t; }" : "=r"(a) : "l"(p));
    return a;
}
__device__ __forceinline__ float sigm(float x) {
    return __fdividef(1.0f, 1.0f + __expf(-x));
}
__device__ __forceinline__ float tanhe(float x) {
    return __fdividef(2.0f, 1.0f + __expf(-2.0f * x)) - 1.0f;
}

#define LDSM4(r0,r1,r2,r3,a) \
    asm volatile("ldmatrix.sync.aligned.m8n8.x4.shared.b16 {%0,%1,%2,%3}, [%4];" \
        : "=r"(r0), "=r"(r1), "=r"(r2), "=r"(r3) : "r"(a))
#define MMA(d,a0,a1,a2,a3,b0,b1) \
    asm volatile("mma.sync.aligned.m16n8k16.row.col.f32.f16.f16.f32 " \
        "{%0,%1,%2,%3},{%4,%5,%6,%7},{%8,%9},{%0,%1,%2,%3};" \
        : "+f"((d)[0]), "+f"((d)[1]), "+f"((d)[2]), "+f"((d)[3]) \
        : "r"(a0), "r"(a1), "r"(a2), "r"(a3), "r"(b0), "r"(b1))

#define CP_A16(sm, gp) \
    asm volatile("cp.async.cg.shared.global [%0], [%1], 16;" :: "r"(sm), "l"(gp) : "memory")
#define CP_COMMIT() asm volatile("cp.async.commit_group;" ::: "memory")
#define CP_WAIT1()  asm volatile("cp.async.wait_group 1;" ::: "memory")
#define CP_WAIT0()  asm volatile("cp.async.wait_group 0;" ::: "memory")

/* warp tile M32xN16: two A 16-row frags, one LDSM4 B covering n16xk16 */
__device__ __forceinline__ void run_gemm(unsigned aA0, unsigned aA1, unsigned wA,
                                         int ksteps, float acc[2][2][4]) {
#pragma unroll 2
    for (int ks = 0; ks < ksteps; ks++) {
        unsigned p0,p1,p2,p3, q0,q1,q2,q3, b0,b1,b2,b3;
        LDSM4(p0,p1,p2,p3, aA0);
        LDSM4(q0,q1,q2,q3, aA1);
        LDSM4(b0,b1,b2,b3, wA);
        MMA(acc[0][0], p0,p1,p2,p3, b0,b1);
        MMA(acc[0][1], p0,p1,p2,p3, b2,b3);
        MMA(acc[1][0], q0,q1,q2,q3, b0,b1);
        MMA(acc[1][1], q0,q1,q2,q3, b2,b3);
        aA0 += 32; aA1 += 32; wA += 32;
    }
}

/* fused: same A fragments feed two B operands (W0 -> acc0, W1 -> acc1) */
__device__ __forceinline__ void run_gemm_dual(unsigned aA0, unsigned aA1,
                                              unsigned w0A, unsigned w1A,
                                              int ksteps,
                                              float acc0[2][2][4],
                                              float acc1[2][2][4]) {
#pragma unroll 2
    for (int ks = 0; ks < ksteps; ks++) {
        unsigned p0,p1,p2,p3, q0,q1,q2,q3;
        unsigned b0,b1,b2,b3, d0,d1,d2,d3;
        LDSM4(p0,p1,p2,p3, aA0);
        LDSM4(q0,q1,q2,q3, aA1);
        LDSM4(b0,b1,b2,b3, w0A);
        LDSM4(d0,d1,d2,d3, w1A);
        MMA(acc0[0][0], p0,p1,p2,p3, b0,b1);
        MMA(acc0[0][1], p0,p1,p2,p3, b2,b3);
        MMA(acc0[1][0], q0,q1,q2,q3, b0,b1);
        MMA(acc0[1][1], q0,q1,q2,q3, b2,b3);
        MMA(acc1[0][0], p0,p1,p2,p3, d0,d1);
        MMA(acc1[0][1], p0,p1,p2,p3, d2,d3);
        MMA(acc1[1][0], q0,q1,q2,q3, d0,d1);
        MMA(acc1[1][1], q0,q1,q2,q3, d2,d3);
        aA0 += 32; aA1 += 32; w0A += 32; w1A += 32;
    }
}

__device__ __forceinline__ void frag_store(float* GBf, const float acc[2][2][4],
                                           int mh, int nq, int lane) {
#pragma unroll
    for (int mt = 0; mt < 2; mt++)
#pragma unroll
        for (int nt = 0; nt < 2; nt++) {
            int m = mh * 32 + mt * 16 + (lane >> 2);
            int n = nq * 16 + nt * 8 + (lane & 3) * 2;
            *(float2*)&GBf[m * 66 + n]       = make_float2(acc[mt][nt][0], acc[mt][nt][1]);
            *(float2*)&GBf[(m + 8) * 66 + n] = make_float2(acc[mt][nt][2], acc[mt][nt][3]);
        }
}

/* split barrier: release arrive / acquire wait on a monotonic counter */
__device__ __forceinline__ void g_arrive(unsigned* c) {
    __threadfence();
    __syncthreads();
    if (threadIdx.x == 0)
        asm volatile("red.release.gpu.global.add.u32 [%0], %1;" :: "l"(c), "r"(1u) : "memory");
}
__device__ __forceinline__ void g_wait(unsigned* c, unsigned target) {
    if (threadIdx.x == 0) {
        unsigned v;
        do {
            asm volatile("ld.acquire.gpu.global.u32 %0, [%1];" : "=r"(v) : "l"(c) : "memory");
        } while (v < target);
    }
    __syncthreads();
}

/* stage x_t as hi/res fp16 pair into A0 cols 256..287 (256 threads) */
__device__ __forceinline__ void stage_x(char* smem, const float* x, int group,
                                        int t, int tid) {
    int row = tid >> 2, kq = (tid & 3) * 4;
    const float4 v = __ldg((const float4*)
        (x + (size_t)(group * 64 + row) * T_ * D_ + (size_t)t * D_ + kq));
    __half h0 = __float2half(v.x), h1 = __float2half(v.y),
           h2 = __float2half(v.z), h3 = __float2half(v.w);
    float r0 = v.x - __half2float(h0), r1 = v.y - __half2float(h1),
          r2 = v.z - __half2float(h2), r3 = v.w - __half2float(h3);
    __half2 hA = __halves2half2(h0, h1), hB = __halves2half2(h2, h3);
    __half2 rA = __floats2half2_rn(r0, r1), rB = __floats2half2_rn(r2, r3);
    char* base = smem + A0_OFF + row * (S0 * 2);
    *(uint2*)(base + (256 + kq) * 2) = make_uint2(*(unsigned*)&hA, *(unsigned*)&hB);
    *(uint2*)(base + (272 + kq) * 2) = make_uint2(*(unsigned*)&rA, *(unsigned*)&rB);
}

/* ---- main persistent kernel: 128 CTAs = 8 groups x 16 ranks, 256 thr ----
   R13 protocol (layer-pipelined, one barrier/step, cp.async split groups,
   x-part in barrier shadow) + R15 fusion: GEMM0 h-part and GEMM1 h0-part
   share A fragments in one dual-B loop.                                   */
__global__ void __launch_bounds__(256, 1)
lstm_main(const float* __restrict__ x,
          const float* __restrict__ Wih0, const float* __restrict__ Whh0,
          const float* __restrict__ Wih1, const float* __restrict__ Whh1,
          const float* __restrict__ bih0, const float* __restrict__ bhh0,
          const float* __restrict__ bih1, const float* __restrict__ bhh1,
          const float* __restrict__ Wo, const float* __restrict__ bo,
          float* __restrict__ out)
{
    extern __shared__ char smem[];
    const int tid  = threadIdx.x;
    const int lane = tid & 31;
    const int wid  = tid >> 5;
    const int mh = wid & 1, nq = wid >> 1;
    const int group = blockIdx.x >> 4;
    const int rank  = blockIdx.x & 15;
    const int jl = tid & 15;
    const int rgrp = tid >> 4;            /* 0..15, owns rows 4*rgrp..4*rgrp+3 */

    __half* W0s = (__half*)(smem + W0_OFF);
    __half* W1s = (__half*)(smem + W1_OFF);
    float*  GB0 = (float*)(smem + GB0_OFF);
    float*  GB1 = (float*)(smem + GB1_OFF);
    float*  b0s = (float*)(smem + BS_OFF);
    float*  b1s = b0s + 64;

    unsigned* cB = &g_cnt[group];

    /* ---- one-time weight staging ---- */
    for (int e = tid; e < 64 * S0; e += 256) {
        int n = e / S0, k = e - n * S0;
        int wr = (n >> 4) * H_ + rank * 16 + (n & 15);
        float v = 0.0f;
        if (k < 256)      v = Whh0[wr * H_ + k];
        else if (k < 272) v = Wih0[wr * D_ + (k - 256)];
        else if (k < 288) v = Wih0[wr * D_ + (k - 272)];
        W0s[e] = __float2half(v);
    }
    for (int e = tid; e < 64 * S1; e += 256) {
        int n = e / S1, k = e - n * S1;
        int wr = (n >> 4) * H_ + rank * 16 + (n & 15);
        float v = 0.0f;
        if (k < 256)      v = Wih1[wr * H_ + k];
        else if (k < 512) v = Whh1[wr * H_ + (k - 256)];
        W1s[e] = __float2half(v);
    }
    if (tid < 64) {
        int wr = (tid >> 4) * H_ + rank * 16 + (tid & 15);
        b0s[tid] = bih0[wr] + bhh0[wr];
        b1s[tid] = bih1[wr] + bhh1[wr];
    }
    const float woreg = __ldg(Wo + rank * 16 + jl);
    const float bo0   = __ldg(bo);

    /* ---- zero this group's output rows (head atomicAdd at it>=1 is gated
            behind B(0), which follows every rank's prologue) ---- */
    {
        float* ob = out + (size_t)group * 64 * T_;
        for (int i = rank * 256 + tid; i < 64 * T_; i += 4096) ob[i] = 0.0f;
    }

    /* ---- initial A0 <- h0 init (fp32 master -> fp16, race-free: g_h0f is
            never written by this kernel); stage x(0) ---- */
    for (int e = tid; e < 64 * 128; e += 256) {   /* 64 rows x 128 half2 */
        int row = e >> 7, c2 = e & 127;
        const float2 v = *(const float2*)
            (g_h0f + (size_t)(group * 64 + row) * H_ + c2 * 2);
        __half2 h = __floats2half2_rn(v.x, v.y);
        *(unsigned*)(smem + A0_OFF + row * (S0 * 2) + c2 * 4) = *(unsigned*)&h;
    }
    stage_x(smem, x, group, 0, tid);

    /* ---- c-state: 4 rows x 1 j per thread ---- */
    float c0[4], c1[4];
#pragma unroll
    for (int rr = 0; rr < 4; rr++) {
        float v = g_h0f[(size_t)(group * 64 + rgrp * 4 + rr) * H_ + rank * 16 + jl];
        c0[rr] = v; c1[rr] = v;
    }
    __syncthreads();

    /* ldmatrix addressing */
    const unsigned sb = su32(smem);
    const int aRow = mh * 32 + (lane & 7) + ((lane >> 3) & 1) * 8;
    const int aCol = (lane >> 4) * 8;
    const unsigned a0m0 = sb + A0_OFF + (unsigned)(aRow * S0 + aCol) * 2;
    const unsigned a0m1 = sb + A0_OFF + (unsigned)((aRow + 16) * S0 + aCol) * 2;
    const unsigned a1m0 = sb + A1_OFF + (unsigned)(aRow * S1N + aCol) * 2;
    const unsigned a1m1 = sb + A1_OFF + (unsigned)((aRow + 16) * S1N + aCol) * 2;
    const int nrow = nq * 16 + ((lane >> 4) & 1) * 8 + (lane & 7);
    const int wCol = ((lane >> 3) & 1) * 8;
    const unsigned w0a = sb + W0_OFF + (unsigned)(nrow * S0 + wCol) * 2;
    const unsigned w1a = sb + W1_OFF + (unsigned)(nrow * S1 + wCol) * 2;

    /* acc0 persists across the loop boundary: x-part is pre-accumulated in
       the barrier shadow; h-part completes it next iteration. */
    float acc0[2][2][4];
#pragma unroll
    for (int a = 0; a < 2; a++)
#pragma unroll
        for (int b = 0; b < 2; b++)
#pragma unroll
            for (int c = 0; c < 4; c++) acc0[a][b][c] = 0.0f;
    run_gemm(a0m0 + 512, a0m1 + 512, w0a + 512, 2, acc0);   /* x(0) part */

    unsigned bt = 0;

    for (int it = 0; it <= T_; it++) {
        /* A0 (h0(it-1)) ready: only the first commit-group must land */
        CP_WAIT1();
        __syncthreads();

        float acc1[2][2][4];
        if (it > 0) {
#pragma unroll
            for (int a = 0; a < 2; a++)
#pragma unroll
                for (int b = 0; b < 2; b++)
#pragma unroll
                    for (int c = 0; c < 4; c++) acc1[a][b][c] = 0.0f;
        }

        /* fused GEMM0 h-part + GEMM1 h0-part (same A fragments) */
        if (it > 0 && it < T_) {
            run_gemm_dual(a0m0, a0m1, w0a, w1a, 16, acc0, acc1);
            frag_store(GB0, acc0, mh, nq, lane);
        } else if (it == 0) {
            run_gemm(a0m0, a0m1, w0a, 16, acc0);
            frag_store(GB0, acc0, mh, nq, lane);
        } else { /* it == T_: only GEMM1's h0-part */
            run_gemm(a0m0, a0m1, w1a, 16, acc1);
        }

        /* A1 (h1(it-2)) ready */
        CP_WAIT0();
        __syncthreads();

        /* GEMM1 h1-part: h1(it-2) @ Whh1^T */
        if (it > 0) {
            run_gemm(a1m0, a1m1, w1a + 512, 16, acc1);
            frag_store(GB1, acc1, mh, nq, lane);
        }
        __syncthreads();

        /* epilogue 0 -> h0(it), publish to parity buffer it&1 */
        if (it < T_) {
            __half* dst = g_h0x + (size_t)(it & 1) * NBH;
#pragma unroll
            for (int rr = 0; rr < 4; rr++) {
                int r = rgrp * 4 + rr;
                float gi = GB0[r * 66 +      jl] + b0s[jl];
                float gf = GB0[r * 66 + 16 + jl] + b0s[16 + jl];
                float gg = GB0[r * 66 + 32 + jl] + b0s[32 + jl];
                float go = GB0[r * 66 + 48 + jl] + b0s[48 + jl];
                float iv = sigm(gi), fv = sigm(gf), gv = tanhe(gg), ov = sigm(go);
                c0[rr] = fv * c0[rr] + iv * gv;
                dst[(size_t)(group * 64 + r) * H_ + rank * 16 + jl] =
                    __float2half(ov * tanhe(c0[rr]));
            }
        }

        /* epilogue 1 -> h1(it-1), publish to parity (it-1)&1, head out(it-1) */
        if (it > 0) {
            __half* dst = g_h1x + (size_t)((it - 1) & 1) * NBH;
            float p[4];
#pragma unroll
            for (int rr = 0; rr < 4; rr++) {
                int r = rgrp * 4 + rr;
                float gi = GB1[r * 66 +      jl] + b1s[jl];
                float gf = GB1[r * 66 + 16 + jl] + b1s[16 + jl];
                float gg = GB1[r * 66 + 32 + jl] + b1s[32 + jl];
                float go = GB1[r * 66 + 48 + jl] + b1s[48 + jl];
                float iv = sigm(gi), fv = sigm(gf), gv = tanhe(gg), ov = sigm(go);
                c1[rr] = fv * c1[rr] + iv * gv;
                float h = ov * tanhe(c1[rr]);
                dst[(size_t)(group * 64 + r) * H_ + rank * 16 + jl] = __float2half(h);
                p[rr] = h * woreg;
            }
#pragma unroll
            for (int off = 1; off < 16; off <<= 1)
#pragma unroll
                for (int rr = 0; rr < 4; rr++)
                    p[rr] += __shfl_xor_sync(0xffffffffu, p[rr], off);
            if (jl == 0) {
#pragma unroll
                for (int rr = 0; rr < 4; rr++) {
                    float v = p[rr];
                    if (rank == 0) v += bo0;
                    atomicAdd(&out[(size_t)(group * 64 + rgrp * 4 + rr) * T_ + (it - 1)], v);
                }
            }
        }

        if (it == T_) break;

        /* arrive, then fill the barrier shadow with independent work:
           stage x(it+1) + GEMM0(it+1) x-part (reads only x-cols + W0). */
        g_arrive(cB);
        if (it + 1 < T_) stage_x(smem, x, group, it + 1, tid);
        __syncthreads();
#pragma unroll
        for (int a = 0; a < 2; a++)
#pragma unroll
            for (int b = 0; b < 2; b++)
#pragma unroll
                for (int c = 0; c < 4; c++) acc0[a][b][c] = 0.0f;
        if (it + 1 < T_)
            run_gemm(a0m0 + 512, a0m1 + 512, w0a + 512, 2, acc0);

        bt += 16;
        g_wait(cB, bt);

        /* async reload: A0 <- h0(it) [group 0], A1 <- h1(it-1) [group 1].
           Next iter: GEMM0 waits group 0 only; A1 hides behind GEMM0+GEMM1a. */
        {
            const __half* s0 = g_h0x + (size_t)(it & 1) * NBH;
            const __half* s1 = g_h1x + (size_t)((it - 1) & 1) * NBH; /* it=0 -> init */
            for (int e = tid; e < 2048; e += 256) {
                int row = e >> 5, ch = e & 31;
                unsigned dst = sb + A0_OFF + (unsigned)(row * (S0 * 2) + ch * 16);
                CP_A16(dst, (const char*)(s0 + (size_t)(group * 64 + row) * H_) + ch * 16);
            }
            CP_COMMIT();
            for (int e = tid; e < 2048; e += 256) {
                int row = e >> 5, ch = e & 31;
                unsigned dst = sb + A1_OFF + (unsigned)(row * (S1N * 2) + ch * 16);
                CP_A16(dst, (const char*)(s1 + (size_t)(group * 64 + row) * H_) + ch * 16);
            }
            CP_COMMIT();
        }
        /* no sync here: next iteration begins with CP_WAIT1 + __syncthreads */
    }
}

/* ---------------- launch ---------------- */
extern "C" void kernel_launch(void* const* d_in, const int* in_sizes, int n_in,
                              void* d_out, int out_size) {
    const float* x    = (const float*)d_in[0];
    const float* xst  = (const float*)d_in[1];
    const float* Wih0 = (const float*)d_in[2];
    const float* Whh0 = (const float*)d_in[3];
    const float* bih0 = (const float*)d_in[4];
    const float* bhh0 = (const float*)d_in[5];
    const float* Wih1 = (const float*)d_in[6];
    const float* Whh1 = (const float*)d_in[7];
    const float* bih1 = (const float*)d_in[8];
    const float* bhh1 = (const float*)d_in[9];
    const float* Ws   = (const float*)d_in[10];
    const float* bs   = (const float*)d_in[11];
    const float* Wo   = (const float*)d_in[12];
    const float* bo   = (const float*)d_in[13];
    float* out = (float*)d_out;

    cudaFuncSetAttribute(lstm_main, cudaFuncAttributeMaxDynamicSharedMemorySize,
                         SMEM_BYTES);

    k_h0<<<(NBH + 255) / 256, 256>>>(xst, Ws, bs);
    lstm_main<<<128, 256, SMEM_BYTES>>>(x, Wih0, Whh0, Wih1, Whh1,
                                        bih0, bhh0, bih1, bhh1, Wo, bo, out);
}